// round 15
// baseline (speedup 1.0000x reference)
#include <cuda_runtime.h>
#include <cuda_fp16.h>
#include <cstdint>
#include <math.h>

#define NTOK 4096
#define DIM  1024
#define HID  4096
#define NEXP 8
#define TOPK 2
#define NASSIGN (NTOK * TOPK)        // 8192
#define ROWPAD  (NASSIGN + 128)      // pad rows for ragged M-tiles

// ---------------- scratch (static device globals; no allocations) -----------
__device__ int    g_cnt[NEXP];
__device__ int    g_off[NEXP];
__device__ int    g_fill[NEXP];
__device__ int    g_texp[NASSIGN];
__device__ float  g_twt[NASSIGN];
__device__ int    g_rowtok[NASSIGN];
__device__ float  g_rowwt[NASSIGN];
__device__ int    g_mtoff[NEXP + 1];                // m-tile prefix per expert
__device__ int    g_ctr1, g_ctr2;                   // persistent tile counters
__device__ __half g_xg  [(size_t)ROWPAD * DIM];     // gathered, weighted x (fp16)
__device__ __half g_hbuf[(size_t)ROWPAD * HID];     // hidden activations (fp16)
__device__ __half g_w1h [(size_t)NEXP * HID * DIM]; // W1^T fp16: [e][n=H][k=D]
__device__ __half g_w2h [(size_t)NEXP * DIM * HID]; // W2^T fp16: [e][n=D][k=H]

// ---------------- helpers ----------------------------------------------------
__device__ __forceinline__ void mma_f16(float* d, const uint32_t* a, const uint32_t* b) {
    asm volatile(
        "mma.sync.aligned.m16n8k16.row.col.f32.f16.f16.f32 "
        "{%0,%1,%2,%3}, {%4,%5,%6,%7}, {%8,%9}, {%0,%1,%2,%3};"
        : "+f"(d[0]), "+f"(d[1]), "+f"(d[2]), "+f"(d[3])
        : "r"(a[0]), "r"(a[1]), "r"(a[2]), "r"(a[3]), "r"(b[0]), "r"(b[1]));
}
__device__ __forceinline__ void ldsm4(uint32_t* r, uint32_t addr) {
    asm volatile("ldmatrix.sync.aligned.m8n8.x4.shared.b16 {%0,%1,%2,%3}, [%4];"
                 : "=r"(r[0]), "=r"(r[1]), "=r"(r[2]), "=r"(r[3]) : "r"(addr));
}
__device__ __forceinline__ uint32_t smem_u32(const void* p) {
    uint32_t a;
    asm("{ .reg .u64 t; cvta.to.shared.u64 t, %1; cvt.u32.u64 %0, t; }" : "=r"(a) : "l"(p));
    return a;
}
__device__ __forceinline__ void cpasync16(uint32_t dst, const void* src) {
    asm volatile("cp.async.cg.shared.global [%0], [%1], 16;" :: "r"(dst), "l"(src) : "memory");
}
#define CP_COMMIT() asm volatile("cp.async.commit_group;" ::: "memory")
#define CP_WAIT(n)  asm volatile("cp.async.wait_group %0;" :: "n"(n) : "memory")

// ---------------- routing kernels -------------------------------------------
__global__ void reset_kernel() {
    int t = threadIdx.x;
    if (t < NEXP) { g_cnt[t] = 0; g_fill[t] = 0; }
    if (t == 0) { g_ctr1 = 0; g_ctr2 = 0; }
}

__global__ void zero_out_kernel(float* __restrict__ out) {
    int i = blockIdx.x * blockDim.x + threadIdx.x;
    ((float4*)out)[i] = make_float4(0.f, 0.f, 0.f, 0.f);
}

__global__ void gating_kernel(const float* __restrict__ x,
                              const float* __restrict__ gw,
                              const float* __restrict__ gb,
                              float* __restrict__ out_logits) {
    const int n = blockIdx.x;
    const float* xr = x + (size_t)n * DIM;
    float acc[NEXP];
#pragma unroll
    for (int e = 0; e < NEXP; e++) acc[e] = 0.f;
    for (int d = threadIdx.x; d < DIM; d += blockDim.x) {
        float xv = xr[d];
        const float* g = gw + (size_t)d * NEXP;
#pragma unroll
        for (int e = 0; e < NEXP; e++) acc[e] = fmaf(xv, g[e], acc[e]);
    }
    __shared__ float red[256][NEXP];
#pragma unroll
    for (int e = 0; e < NEXP; e++) red[threadIdx.x][e] = acc[e];
    __syncthreads();
    for (int s = 128; s > 0; s >>= 1) {
        if (threadIdx.x < s)
#pragma unroll
            for (int e = 0; e < NEXP; e++) red[threadIdx.x][e] += red[threadIdx.x + s][e];
        __syncthreads();
    }
    if (threadIdx.x == 0) {
        float l[NEXP];
#pragma unroll
        for (int e = 0; e < NEXP; e++) {
            l[e] = red[0][e] + gb[e];
            out_logits[(size_t)n * NEXP + e] = l[e];
        }
        int i0 = 0;
#pragma unroll
        for (int e = 1; e < NEXP; e++) if (l[e] > l[i0]) i0 = e;
        int i1 = -1;
#pragma unroll
        for (int e = 0; e < NEXP; e++)
            if (e != i0 && (i1 < 0 || l[e] > l[i1])) i1 = e;
        float ex = __expf(l[i1] - l[i0]);
        float w0 = 1.f / (1.f + ex);
        float w1 = ex / (1.f + ex);
        g_texp[n * 2 + 0] = i0; g_twt[n * 2 + 0] = w0;
        g_texp[n * 2 + 1] = i1; g_twt[n * 2 + 1] = w1;
        atomicAdd(&g_cnt[i0], 1);
        atomicAdd(&g_cnt[i1], 1);
    }
}

__global__ void offsets_kernel() {
    if (threadIdx.x == 0) {
        int s = 0, mt = 0;
        for (int e = 0; e < NEXP; e++) {
            g_off[e] = s;
            g_mtoff[e] = mt;
            s  += g_cnt[e];
            mt += (g_cnt[e] + 127) >> 7;
        }
        g_mtoff[NEXP] = mt;
    }
}

__global__ void fill_kernel() {
    int n = blockIdx.x * blockDim.x + threadIdx.x;
    if (n >= NTOK) return;
#pragma unroll
    for (int s = 0; s < TOPK; s++) {
        int e = g_texp[n * 2 + s];
        int pos = atomicAdd(&g_fill[e], 1);
        int row = g_off[e] + pos;
        g_rowtok[row] = n;
        g_rowwt[row]  = g_twt[n * 2 + s];
    }
}

// gather + gate-weight + fp16: xg[row] = h(x[tok] * wt)
__global__ void gather_kernel(const float* __restrict__ x) {
    int row = blockIdx.x;
    int tok = g_rowtok[row];
    float wt = g_rowwt[row];
    const float4* xp = (const float4*)(x + (size_t)tok * DIM);
    float4 v = xp[threadIdx.x];
    __half2 h0 = __floats2half2_rn(v.x * wt, v.y * wt);
    __half2 h1 = __floats2half2_rn(v.z * wt, v.w * wt);
    __half2* gp = (__half2*)(g_xg + (size_t)row * DIM);
    gp[threadIdx.x * 2 + 0] = h0;
    gp[threadIdx.x * 2 + 1] = h1;
}

// fast cast+transpose: src[e][R][C] f32 -> dst[e][C][R] fp16
__global__ void castT_kernel(const float* __restrict__ src, __half* __restrict__ dst,
                             int R, int C) {
    __shared__ __half s[64][66];
    const int e = blockIdx.z;
    src += (size_t)e * R * C;
    dst += (size_t)e * R * C;
    const int c0 = blockIdx.x * 64, r0 = blockIdx.y * 64;
    const int tid = threadIdx.x;

    const int rr = tid >> 4, cc = (tid & 15) * 4;
#pragma unroll
    for (int i = 0; i < 4; i++) {
        int r = rr + i * 16;
        float4 v = *(const float4*)(src + (size_t)(r0 + r) * C + c0 + cc);
        s[cc + 0][r] = __float2half_rn(v.x);
        s[cc + 1][r] = __float2half_rn(v.y);
        s[cc + 2][r] = __float2half_rn(v.z);
        s[cc + 3][r] = __float2half_rn(v.w);
    }
    __syncthreads();

    const int co = tid >> 4, ro = (tid & 15) * 4;
#pragma unroll
    for (int i = 0; i < 4; i++) {
        int c = co + i * 16;
        __half2 a = *(__half2*)&s[c][ro];
        __half2 b = *(__half2*)&s[c][ro + 2];
        uint2 u;
        u.x = *(uint32_t*)&a;
        u.y = *(uint32_t*)&b;
        *(uint2*)(dst + (size_t)(c0 + c) * R + r0 + ro) = u;
    }
}

// ---------------- persistent fp16 mma.sync grouped GEMM ----------------------
// Tiles pulled from an atomic counter; consecutive tiles share the same B n-tile.
// CTA tile 128(M) x NTILE(N) x 32(K); 8 warps (2M x 4N).
// MODE 0: out = h(gelu(acc + b1)) -> g_hbuf
// MODE 1: atomicAdd(out[tok], (acc + b2) * wt)   (2 commutative adds per element)
#define APH 40                                   // smem pitch (halves), ldmatrix conflict-free

template <int KD, int NB, int NTILE, int MODE, int OCC>
__global__ __launch_bounds__(256, OCC)
void gemm_tc(const __half* __restrict__ Abase,
             const __half* __restrict__ W,
             const float* __restrict__ bias,
             float* __restrict__ out,
             int* __restrict__ ctr) {
    constexpr int ATILE_B = 128 * APH * 2;
    constexpr int BTILE_B = NTILE * APH * 2;
    constexpr int STAGE_B = ATILE_B + BTILE_B;
    constexpr int NT = NTILE / 32;
    constexpr int NC = KD / 32;
    constexpr int NTn = NB / NTILE;

    extern __shared__ char smem[];
    __shared__ int s_t;
    const uint32_t sb = smem_u32(smem);
    const int tid  = threadIdx.x;
    const int wid  = tid >> 5;
    const int lane = tid & 31;

    const int mtot   = g_mtoff[NEXP];
    const int ntiles = mtot * NTn;

    const int mbase = (wid & 1) * 64;
    const int nbase = (wid >> 1) * (NTILE / 4);
    const int rA    = lane & 15;
    const int kofsA = (lane >> 4) * 8;
    const int rB    = (lane & 7) + (lane >> 4) * 8;
    const int kofsB = ((lane >> 3) & 1) * 8;
    const uint32_t aOff = (uint32_t)(mbase + rA) * (APH * 2) + kofsA * 2;
    const uint32_t bOff = ATILE_B + (uint32_t)(nbase + rB) * (APH * 2) + kofsB * 2;
    const int ra = lane >> 2, ca = lane & 3;

    for (;;) {
        if (tid == 0) s_t = atomicAdd(ctr, 1);
        __syncthreads();
        const int t = s_t;
        if (t >= ntiles) break;

        const int ntg   = t / mtot;          // B n-tile (shared by consecutive t)
        const int mtIdx = t % mtot;
        int e = 0;
#pragma unroll
        for (int k = 0; k < NEXP - 1; k++)
            if (mtIdx >= g_mtoff[k + 1]) e = k + 1;
        const int mt   = mtIdx - g_mtoff[e];
        const int cnt  = g_cnt[e];
        const int base = g_off[e];
        const int m0   = mt * 128;
        const int n0   = ntg * NTILE;

        const __half* Wg = W + (size_t)e * (size_t)NB * KD;
        const __half* Ag = Abase + (size_t)(base + m0) * KD;

        auto load_chunk = [&](int c, int st) {
            const uint32_t sa = sb + st * STAGE_B;
#pragma unroll
            for (int w = 0; w < 2; w++) {
                int u = tid + w * 256;
                int r = u >> 2, k8 = (u & 3) * 8;
                cpasync16(sa + r * (APH * 2) + k8 * 2, Ag + (size_t)r * KD + c * 32 + k8);
            }
            const uint32_t sB = sa + ATILE_B;
#pragma unroll
            for (int w = 0; w < NTILE / 64; w++) {
                int u = tid + w * 256;
                int r = u >> 2, k8 = (u & 3) * 8;
                cpasync16(sB + r * (APH * 2) + k8 * 2, Wg + (size_t)(n0 + r) * KD + c * 32 + k8);
            }
            CP_COMMIT();
        };

        float acc[4][NT][4];
#pragma unroll
        for (int i = 0; i < 4; i++)
#pragma unroll
            for (int j = 0; j < NT; j++)
#pragma unroll
                for (int k = 0; k < 4; k++) acc[i][j][k] = 0.f;

        load_chunk(0, 0);
        load_chunk(1, 1);
        load_chunk(2, 2);

        for (int c = 0; c < NC; c++) {
            CP_WAIT(2);
            __syncthreads();
            if (c + 3 < NC) load_chunk(c + 3, (c + 3) & 3);
            else CP_COMMIT();

            const uint32_t st = sb + (c & 3) * STAGE_B;
#pragma unroll
            for (int kk = 0; kk < 2; kk++) {
                uint32_t a[4][4], b[NT][2];
#pragma unroll
                for (int mtt = 0; mtt < 4; mtt++)
                    ldsm4(a[mtt], st + aOff + mtt * (16 * APH * 2) + kk * 32);
#pragma unroll
                for (int np = 0; np < NT / 2; np++) {
                    uint32_t r[4];
                    ldsm4(r, st + bOff + np * (16 * APH * 2) + kk * 32);
                    b[np * 2 + 0][0] = r[0];
                    b[np * 2 + 0][1] = r[1];
                    b[np * 2 + 1][0] = r[2];
                    b[np * 2 + 1][1] = r[3];
                }
#pragma unroll
                for (int mtt = 0; mtt < 4; mtt++)
#pragma unroll
                    for (int nt = 0; nt < NT; nt++)
                        mma_f16(acc[mtt][nt], a[mtt], b[nt]);
            }
        }

        // epilogue
        const float* bp = bias + (size_t)e * NB + n0;
#pragma unroll
        for (int mtt = 0; mtt < 4; mtt++) {
#pragma unroll
            for (int half = 0; half < 2; half++) {
                int r = m0 + mbase + mtt * 16 + ra + half * 8;
                if (r < cnt) {
#pragma unroll
                    for (int nt = 0; nt < NT; nt++) {
                        int col = nbase + nt * 8 + ca * 2;
                        float v0 = acc[mtt][nt][half * 2 + 0] + bp[col];
                        float v1 = acc[mtt][nt][half * 2 + 1] + bp[col + 1];
                        if (MODE == 0) {
                            v0 = 0.5f * v0 * (1.f + erff(v0 * 0.70710678118654752f));
                            v1 = 0.5f * v1 * (1.f + erff(v1 * 0.70710678118654752f));
                            *(__half2*)(g_hbuf + (size_t)(base + r) * HID + n0 + col) =
                                __floats2half2_rn(v0, v1);
                        } else {
                            float wt = g_rowwt[base + r];
                            int tok  = g_rowtok[base + r];
                            float* op = out + (size_t)tok * DIM + n0 + col;
                            atomicAdd(op + 0, v0 * wt);
                            atomicAdd(op + 1, v1 * wt);
                        }
                    }
                }
            }
        }
    }
}

// ---------------- host -------------------------------------------------------
extern "C" void kernel_launch(void* const* d_in, const int* in_sizes, int n_in,
                              void* d_out, int out_size) {
    const float* x  = (const float*)d_in[0];
    const float* gw = (const float*)d_in[1];
    const float* gb = (const float*)d_in[2];
    const float* w1 = (const float*)d_in[3];
    const float* b1 = (const float*)d_in[4];
    const float* w2 = (const float*)d_in[5];
    const float* b2 = (const float*)d_in[6];

    float* out_final  = (float*)d_out;
    float* out_logits = out_final + (size_t)NTOK * DIM;

    void *p_xg, *p_hb, *p_w1h, *p_w2h, *p_c1, *p_c2;
    cudaGetSymbolAddress(&p_xg,  g_xg);
    cudaGetSymbolAddress(&p_hb,  g_hbuf);
    cudaGetSymbolAddress(&p_w1h, g_w1h);
    cudaGetSymbolAddress(&p_w2h, g_w2h);
    cudaGetSymbolAddress(&p_c1,  g_ctr1);
    cudaGetSymbolAddress(&p_c2,  g_ctr2);

    constexpr int SMEM1 = 4 * (128 + 256) * APH * 2;   // 122880
    constexpr int SMEM2 = 4 * (128 + 128) * APH * 2;   // 81920
    cudaFuncSetAttribute(gemm_tc<DIM, HID, 256, 0, 1>,
                         cudaFuncAttributeMaxDynamicSharedMemorySize, SMEM1);
    cudaFuncSetAttribute(gemm_tc<HID, DIM, 128, 1, 2>,
                         cudaFuncAttributeMaxDynamicSharedMemorySize, SMEM2);

    reset_kernel<<<1, 32>>>();
    zero_out_kernel<<<(NTOK * DIM / 4) / 256, 256>>>(out_final);
    gating_kernel<<<NTOK, 256>>>(x, gw, gb, out_logits);
    offsets_kernel<<<1, 1>>>();
    fill_kernel<<<(NTOK + 255) / 256, 256>>>();
    gather_kernel<<<NASSIGN, 256>>>(x);
    castT_kernel<<<dim3(HID / 64, DIM / 64, NEXP), 256>>>(w1, (__half*)p_w1h, DIM, HID);
    castT_kernel<<<dim3(DIM / 64, HID / 64, NEXP), 256>>>(w2, (__half*)p_w2h, HID, DIM);
    gemm_tc<DIM, HID, 256, 0, 1><<<148, 256, SMEM1>>>(
        (const __half*)p_xg, (const __half*)p_w1h, b1, nullptr, (int*)p_c1);
    gemm_tc<HID, DIM, 128, 1, 2><<<296, 256, SMEM2>>>(
        (const __half*)p_hb, (const __half*)p_w2h, b2, out_final, (int*)p_c2);
}